// round 16
// baseline (speedup 1.0000x reference)
#include <cuda_runtime.h>
#include <cuda_bf16.h>
#include <math.h>
#include <stdint.h>

// Problem constants
#define BB 1024   // batch (edges per direction)
#define NN 1024   // nodes
#define DD 256    // feature dim
#define K3 768    // 3*D

// ---------------- static scratch (no allocations allowed) ----------------
__device__ __nv_bfloat16 g_Hh[2 * BB * DD], g_Hl[2 * BB * DD];   // hidden hi/lo
__device__ float         g_MSG[2 * BB * DD];                     // messages fp32
__device__ __nv_bfloat16 g_AGGh[NN * DD], g_AGGl[NN * DD];       // segment mean hi/lo
__device__ float         g_G[2 * NN * K3];                       // gi | gh fp32
__device__ int           g_CNT[NN];

// ---------------- fp32 -> bf16 hi/lo split ----------------
__device__ __forceinline__ void split_bf16(float v, __nv_bfloat16& h, __nv_bfloat16& l) {
    h = __float2bfloat16(v);
    l = __float2bfloat16(v - __bfloat162float(h));
}
__device__ __forceinline__ uint32_t pack2(__nv_bfloat16 a, __nv_bfloat16 b) {
    __nv_bfloat162 t; t.x = a; t.y = b;
    return *reinterpret_cast<uint32_t*>(&t);
}

// ---------------- mma.sync bf16 helper ----------------
__device__ __forceinline__ void mma_bf16(float* c, const uint32_t* a, const uint32_t* b) {
    asm volatile(
        "mma.sync.aligned.m16n8k16.row.col.f32.bf16.bf16.f32 "
        "{%0,%1,%2,%3}, {%4,%5,%6,%7}, {%8,%9}, {%0,%1,%2,%3};\n"
        : "+f"(c[0]), "+f"(c[1]), "+f"(c[2]), "+f"(c[3])
        : "r"(a[0]), "r"(a[1]), "r"(a[2]), "r"(a[3]), "r"(b[0]), "r"(b[1]));
}

// ---------------- ldmatrix helper ----------------
__device__ __forceinline__ uint32_t smem_u32(const void* p) {
    return (uint32_t)__cvta_generic_to_shared(p);
}
#define LDSM_X4(r0, r1, r2, r3, addr) \
    asm volatile("ldmatrix.sync.aligned.m8n8.x4.shared.b16 {%0,%1,%2,%3}, [%4];" \
        : "=r"(r0), "=r"(r1), "=r"(r2), "=r"(r3) : "r"(addr))

#define SPAD 40
#define TILE_E (64 * SPAD)

// ---- shared compute core: 3-term split MMA over one staged 64x32 chunk ----
__device__ __forceinline__ void compute_chunk(
    const __nv_bfloat16* sAh, const __nv_bfloat16* sAl,
    const __nv_bfloat16* sWh, const __nv_bfloat16* sWl,
    float acc[2][2][4], int warp_m, int warp_n, int lane) {
    const int arow = warp_m * 32 + (lane & 15);
    const int acol = (lane >> 4) << 3;
    const int brow = warp_n * 16 + ((lane >> 4) << 3) + (lane & 7);
    const int bcol = ((lane >> 3) & 1) << 3;
#pragma unroll
    for (int ks = 0; ks < 2; ks++) {
        const int k0 = ks * 16;
        uint32_t ah[2][4], al[2][4], bh[4], bl[4];
#pragma unroll
        for (int mi = 0; mi < 2; mi++) {
            LDSM_X4(ah[mi][0], ah[mi][1], ah[mi][2], ah[mi][3],
                    smem_u32(&sAh[(arow + mi * 16) * SPAD + k0 + acol]));
            LDSM_X4(al[mi][0], al[mi][1], al[mi][2], al[mi][3],
                    smem_u32(&sAl[(arow + mi * 16) * SPAD + k0 + acol]));
        }
        LDSM_X4(bh[0], bh[1], bh[2], bh[3], smem_u32(&sWh[brow * SPAD + k0 + bcol]));
        LDSM_X4(bl[0], bl[1], bl[2], bl[3], smem_u32(&sWl[brow * SPAD + k0 + bcol]));
#pragma unroll
        for (int mi = 0; mi < 2; mi++)
#pragma unroll
            for (int ni = 0; ni < 2; ni++) {
                mma_bf16(acc[mi][ni], ah[mi], &bh[ni * 2]);
                mma_bf16(acc[mi][ni], ah[mi], &bl[ni * 2]);
                mma_bf16(acc[mi][ni], al[mi], &bh[ni * 2]);
            }
    }
}

// ---- epilogue helper ----
__device__ __forceinline__ void epilogue(
    float acc[2][2][4], const float* __restrict__ bias,
    float* __restrict__ Cf, __nv_bfloat16* __restrict__ Chi, __nv_bfloat16* __restrict__ Clo,
    int row0, int col0, int Nn, int doRelu, int warp_m, int warp_n, int gid, int tig) {
#pragma unroll
    for (int mi = 0; mi < 2; mi++) {
#pragma unroll
        for (int ni = 0; ni < 2; ni++) {
            const int r0 = row0 + warp_m * 32 + mi * 16 + gid;
            const int c  = col0 + warp_n * 16 + ni * 8 + tig * 2;
            const float bx = bias[c];
            const float by = bias[c + 1];
            float v0 = acc[mi][ni][0] + bx;
            float v1 = acc[mi][ni][1] + by;
            float v2 = acc[mi][ni][2] + bx;
            float v3 = acc[mi][ni][3] + by;
            if (doRelu) {
                v0 = fmaxf(v0, 0.0f); v1 = fmaxf(v1, 0.0f);
                v2 = fmaxf(v2, 0.0f); v3 = fmaxf(v3, 0.0f);
            }
            if (Cf) {
                *reinterpret_cast<float2*>(&Cf[(size_t)r0 * Nn + c])       = make_float2(v0, v1);
                *reinterpret_cast<float2*>(&Cf[(size_t)(r0 + 8) * Nn + c]) = make_float2(v2, v3);
            }
            if (Chi) {
                __nv_bfloat16 h0, l0, h1, l1;
                split_bf16(v0, h0, l0); split_bf16(v1, h1, l1);
                *reinterpret_cast<uint32_t*>(&Chi[(size_t)r0 * Nn + c]) = pack2(h0, h1);
                *reinterpret_cast<uint32_t*>(&Clo[(size_t)r0 * Nn + c]) = pack2(l0, l1);
                split_bf16(v2, h0, l0); split_bf16(v3, h1, l1);
                *reinterpret_cast<uint32_t*>(&Chi[(size_t)(r0 + 8) * Nn + c]) = pack2(h0, h1);
                *reinterpret_cast<uint32_t*>(&Clo[(size_t)(r0 + 8) * Nn + c]) = pack2(l0, l1);
            }
        }
    }
}

// ---- fp32 register pair + split-store ----
struct FpRegs { float4 f0, f1; };

__device__ __forceinline__ void store_fp(
    __nv_bfloat16* sh, __nv_bfloat16* sl, const FpRegs& r, int lr, int lk) {
    __nv_bfloat16 h0,l0,h1,l1,h2,l2,h3,l3,h4,l4,h5,l5,h6,l6,h7,l7;
    split_bf16(r.f0.x, h0, l0); split_bf16(r.f0.y, h1, l1);
    split_bf16(r.f0.z, h2, l2); split_bf16(r.f0.w, h3, l3);
    split_bf16(r.f1.x, h4, l4); split_bf16(r.f1.y, h5, l5);
    split_bf16(r.f1.z, h6, l6); split_bf16(r.f1.w, h7, l7);
    uint4 vh = make_uint4(pack2(h0,h1), pack2(h2,h3), pack2(h4,h5), pack2(h6,h7));
    uint4 vl = make_uint4(pack2(l0,l1), pack2(l2,l3), pack2(l4,l5), pack2(l6,l7));
    *reinterpret_cast<uint4*>(&sh[lr * SPAD + lk]) = vh;
    *reinterpret_cast<uint4*>(&sl[lr * SPAD + lk]) = vl;
}

union LoadRegs {
    struct { uint4 vh, vl; } bf;
    FpRegs fp;
};

__device__ __forceinline__ void load_regs(
    LoadRegs& r,
    const __nv_bfloat16* __restrict__ gh, const __nv_bfloat16* __restrict__ gl,
    const float* __restrict__ gf,
    int grow0, int ld, int kt, int lr, int lk) {
    if (gf) {
        const float* p = &gf[(size_t)(grow0 + lr) * ld + kt + lk];
        r.fp.f0 = *reinterpret_cast<const float4*>(p);
        r.fp.f1 = *reinterpret_cast<const float4*>(p + 4);
    } else {
        r.bf.vh = *reinterpret_cast<const uint4*>(&gh[(size_t)(grow0 + lr) * ld + kt + lk]);
        r.bf.vl = *reinterpret_cast<const uint4*>(&gl[(size_t)(grow0 + lr) * ld + kt + lk]);
    }
}

__device__ __forceinline__ void store_regs(
    __nv_bfloat16* sh, __nv_bfloat16* sl, const LoadRegs& r,
    bool isFp, int lr, int lk) {
    if (isFp) {
        store_fp(sh, sl, r.fp, lr, lk);
    } else {
        *reinterpret_cast<uint4*>(&sh[lr * SPAD + lk]) = r.bf.vh;
        *reinterpret_cast<uint4*>(&sl[lr * SPAD + lk]) = r.bf.vl;
    }
}

// =============== generic GEMM body (device) ===============
struct SmemTiles {
    __nv_bfloat16 sAh[2][TILE_E];
    __nv_bfloat16 sAl[2][TILE_E];
    __nv_bfloat16 sWh[2][TILE_E];
    __nv_bfloat16 sWl[2][TILE_E];
};

__device__ __forceinline__ void gemm_body(
    SmemTiles& sm,
    const __nv_bfloat16* __restrict__ Ah, const __nv_bfloat16* __restrict__ Al,
    const float* __restrict__ Af,
    const float* __restrict__ Wf,
    const float* __restrict__ bias,
    float* __restrict__ Cf, __nv_bfloat16* __restrict__ Chi, __nv_bfloat16* __restrict__ Clo,
    int arow0, int row0, int col0, int Nn, int Kk, int doRelu) {

    const int tid  = threadIdx.x;
    const int wid  = tid >> 5;
    const int lane = tid & 31;
    const int g8   = lane >> 2;
    const int tig  = lane & 3;
    const int warp_m = wid >> 2;
    const int warp_n = wid & 3;
    const bool aFp = (Af != nullptr);

    float acc[2][2][4];
#pragma unroll
    for (int mi = 0; mi < 2; mi++)
#pragma unroll
        for (int ni = 0; ni < 2; ni++)
#pragma unroll
            for (int j = 0; j < 4; j++) acc[mi][ni][j] = 0.0f;

    const int lr = tid >> 2;
    const int lk = (tid & 3) * 8;

    const int NC = Kk >> 5;
    LoadRegs ra, rw;
    load_regs(ra, Ah, Al, Af, arow0, Kk, 0, lr, lk);
    load_regs(rw, nullptr, nullptr, Wf, col0, Kk, 0, lr, lk);
    store_regs(sm.sAh[0], sm.sAl[0], ra, aFp, lr, lk);
    store_regs(sm.sWh[0], sm.sWl[0], rw, true, lr, lk);
    __syncthreads();

    for (int c = 0; c < NC; c++) {
        const int cur = c & 1;
        const int nxt = cur ^ 1;
        if (c + 1 < NC) {
            const int kt = (c + 1) * 32;
            load_regs(ra, Ah, Al, Af, arow0, Kk, kt, lr, lk);
            load_regs(rw, nullptr, nullptr, Wf, col0, Kk, kt, lr, lk);
        }

        compute_chunk(sm.sAh[cur], sm.sAl[cur], sm.sWh[cur], sm.sWl[cur],
                      acc, warp_m, warp_n, lane);

        if (c + 1 < NC) {
            store_regs(sm.sAh[nxt], sm.sAl[nxt], ra, aFp, lr, lk);
            store_regs(sm.sWh[nxt], sm.sWl[nxt], rw, true, lr, lk);
            __syncthreads();
        }
    }

    epilogue(acc, bias, Cf, Chi, Clo, row0, col0, Nn, doRelu, warp_m, warp_n, g8, tig);
}

// =============== gather-fused GEMM1 body (device) ===============
__device__ __forceinline__ void gemm1_body(
    SmemTiles& sm,
    const float* __restrict__ memory, const float* __restrict__ dtv,
    const int* __restrict__ src, const int* __restrict__ tgt,
    const float* __restrict__ Wf0, const float* __restrict__ Wf1,
    const float* __restrict__ b0, const float* __restrict__ b1,
    __nv_bfloat16* __restrict__ Chi, __nv_bfloat16* __restrict__ Clo,
    int colblk, int rowblk) {

    const int tid  = threadIdx.x;
    const int wid  = tid >> 5;
    const int lane = tid & 31;
    const int g8   = lane >> 2;
    const int tig  = lane & 3;
    const int warp_m = wid >> 2;
    const int warp_n = wid & 3;

    const int row0 = rowblk * 64;
    const int col0 = colblk * 64;
    const bool hi2 = (row0 >= BB);
    const float* __restrict__ Wf = hi2 ? Wf1 : Wf0;
    const float* __restrict__ bias = hi2 ? b1 : b0;
    const int arow0 = row0 - (hi2 ? BB : 0);

    const int lr = tid >> 2;
    const int lk = (tid & 3) * 8;

    const int b = arow0 + lr;
    const int s = src[b];
    const int t = tgt[b];
    const float* base0 = memory + (size_t)(hi2 ? t : s) * DD;
    const float* base1 = memory + (size_t)(hi2 ? s : t) * DD;
    const float* base2 = dtv + ((size_t)b * NN + (hi2 ? t : s)) * DD;

    float acc[2][2][4];
#pragma unroll
    for (int mi = 0; mi < 2; mi++)
#pragma unroll
        for (int ni = 0; ni < 2; ni++)
#pragma unroll
            for (int j = 0; j < 4; j++) acc[mi][ni][j] = 0.0f;

    const int NC = K3 >> 5;
    FpRegs ra, rw;
    {
        const float* p = base0 + lk;
        ra.f0 = *reinterpret_cast<const float4*>(p);
        ra.f1 = *reinterpret_cast<const float4*>(p + 4);
        const float* q = &Wf[(size_t)(col0 + lr) * K3 + lk];
        rw.f0 = *reinterpret_cast<const float4*>(q);
        rw.f1 = *reinterpret_cast<const float4*>(q + 4);
    }
    store_fp(sm.sAh[0], sm.sAl[0], ra, lr, lk);
    store_fp(sm.sWh[0], sm.sWl[0], rw, lr, lk);
    __syncthreads();

    for (int c = 0; c < NC; c++) {
        const int cur = c & 1;
        const int nxt = cur ^ 1;
        if (c + 1 < NC) {
            const int kt = (c + 1) * 32;
            const int reg = kt >> 8;
            const int co  = (kt & 255) + lk;
            const float* p = (reg == 0 ? base0 : (reg == 1 ? base1 : base2)) + co;
            ra.f0 = *reinterpret_cast<const float4*>(p);
            ra.f1 = *reinterpret_cast<const float4*>(p + 4);
            const float* q = &Wf[(size_t)(col0 + lr) * K3 + kt + lk];
            rw.f0 = *reinterpret_cast<const float4*>(q);
            rw.f1 = *reinterpret_cast<const float4*>(q + 4);
        }

        compute_chunk(sm.sAh[cur], sm.sAl[cur], sm.sWh[cur], sm.sWl[cur],
                      acc, warp_m, warp_n, lane);

        if (c + 1 < NC) {
            store_fp(sm.sAh[nxt], sm.sAl[nxt], ra, lr, lk);
            store_fp(sm.sWh[nxt], sm.sWl[nxt], rw, lr, lk);
            __syncthreads();
        }
    }

    epilogue(acc, bias, nullptr, Chi, Clo, row0, col0, DD, 1, warp_m, warp_n, g8, tig);
}

// =============== fused launch: L1 gather-GEMM (128 blocks) + gh GEMM (192) ===
__global__ __launch_bounds__(256) void fused1_kernel(
    const float* __restrict__ memory, const float* __restrict__ dtv,
    const int* __restrict__ src, const int* __restrict__ tgt,
    const float* __restrict__ w1s, const float* __restrict__ w1t,
    const float* __restrict__ b1s, const float* __restrict__ b1t,
    __nv_bfloat16* __restrict__ Hh, __nv_bfloat16* __restrict__ Hl,
    const float* __restrict__ whh, const float* __restrict__ bhh,
    float* __restrict__ Ggh) {

    __shared__ SmemTiles sm;
    const int blk = blockIdx.x;
    if (blk < 128) {
        // L1: grid was (4 cols, 32 rows)
        gemm1_body(sm, memory, dtv, src, tgt, w1s, w1t, b1s, b1t, Hh, Hl,
                   blk & 3, blk >> 2);
    } else {
        // gh = memory @ whh^T + bhh : M=1024, N=768, K=256 -> (12 cols, 16 rows)
        const int g = blk - 128;
        const int colblk = g % 12;
        const int rowblk = g / 12;
        gemm_body(sm, nullptr, nullptr, memory, whh, bhh,
                  Ggh, nullptr, nullptr,
                  rowblk * 64, rowblk * 64, colblk * 64, K3, DD, 0);
    }
}

// =============== dual-half GEMM launcher (layer 2) ===============
__global__ __launch_bounds__(256) void tgemm_kernel(
    const __nv_bfloat16* __restrict__ Ah0, const __nv_bfloat16* __restrict__ Al0,
    const __nv_bfloat16* __restrict__ Ah1, const __nv_bfloat16* __restrict__ Al1,
    const float* __restrict__ Wf0, const float* __restrict__ Wf1,
    const float* __restrict__ b0, const float* __restrict__ b1,
    float* __restrict__ Cf, __nv_bfloat16* __restrict__ Chi, __nv_bfloat16* __restrict__ Clo,
    int halfM, int Nn, int Kk, int doRelu) {

    __shared__ SmemTiles sm;
    const int row0 = blockIdx.y * 64;
    const int col0 = blockIdx.x * 64;
    const bool hi2 = (row0 >= halfM);
    gemm_body(sm,
              hi2 ? Ah1 : Ah0, hi2 ? Al1 : Al0, nullptr,
              hi2 ? Wf1 : Wf0, hi2 ? b1 : b0,
              Cf, Chi, Clo,
              row0 - (hi2 ? halfM : 0), row0, col0, Nn, Kk, doRelu);
}

// ---------------- deterministic segment mean (warp-per-node) ----------------
__global__ __launch_bounds__(256) void segment_kernel(const int* __restrict__ src,
                                                      const int* __restrict__ tgt) {
    __shared__ int s_ids[2 * BB];
    const int tid = threadIdx.x;
    const int wid = tid >> 5;
    const int lid = tid & 31;
    const int node = blockIdx.x * 8 + wid;

#pragma unroll
    for (int i = 0; i < 8; i++) {
        int e = tid + i * 256;
        s_ids[e] = (e < BB) ? src[e] : tgt[e - BB];
    }
    __syncthreads();

    float sum[8] = {0, 0, 0, 0, 0, 0, 0, 0};
    int cnt = 0;
#pragma unroll 4
    for (int base = 0; base < 2 * BB; base += 32) {
        int v = s_ids[base + lid];
        unsigned m = __ballot_sync(0xffffffffu, v == node);
        while (m) {
            int bpos = __ffs(m) - 1;
            m &= m - 1;
            int e = base + bpos;
            const float4* p = reinterpret_cast<const float4*>(&g_MSG[(size_t)e * DD + lid * 8]);
            float4 a = p[0];
            float4 q = p[1];
            sum[0] += a.x; sum[1] += a.y; sum[2] += a.z; sum[3] += a.w;
            sum[4] += q.x; sum[5] += q.y; sum[6] += q.z; sum[7] += q.w;
            cnt++;
        }
    }

    const float denom = (cnt > 0) ? (float)cnt : 1.0f;
    uint32_t ph[4], pl[4];
#pragma unroll
    for (int j = 0; j < 4; j++) {
        __nv_bfloat16 h0, l0, h1, l1;
        split_bf16(sum[2 * j] / denom, h0, l0);
        split_bf16(sum[2 * j + 1] / denom, h1, l1);
        ph[j] = pack2(h0, h1);
        pl[j] = pack2(l0, l1);
    }
    *reinterpret_cast<uint4*>(&g_AGGh[(size_t)node * DD + lid * 8]) =
        make_uint4(ph[0], ph[1], ph[2], ph[3]);
    *reinterpret_cast<uint4*>(&g_AGGl[(size_t)node * DD + lid * 8]) =
        make_uint4(pl[0], pl[1], pl[2], pl[3]);
    if (lid == 0) g_CNT[node] = cnt;
}

// ---------------- GRU gates + masked write ----------------
__global__ void gate_kernel(const float* __restrict__ memory,
                            float* __restrict__ out) {
    const int n = blockIdx.x;
    const int d = threadIdx.x;
    const float* gi = g_G + (size_t)n * K3;
    const float* gh = g_G + (size_t)(NN + n) * K3;

    float r  = 1.0f / (1.0f + expf(-(gi[d] + gh[d])));
    float z  = 1.0f / (1.0f + expf(-(gi[DD + d] + gh[DD + d])));
    float nn = tanhf(gi[2 * DD + d] + r * gh[2 * DD + d]);
    float h  = memory[(size_t)n * DD + d];
    float nv = (1.0f - z) * nn + z * h;
    out[(size_t)n * DD + d] = (g_CNT[n] > 0) ? nv : h;
}

// ---------------- launch ----------------
extern "C" void kernel_launch(void* const* d_in, const int* in_sizes, int n_in,
                              void* d_out, int out_size) {
    const float* memory  = (const float*)d_in[0];
    const int*   source  = (const int*)d_in[1];
    const int*   target  = (const int*)d_in[2];
    const float* dtv     = (const float*)d_in[3];
    const float* src_w1  = (const float*)d_in[4];
    const float* src_b1  = (const float*)d_in[5];
    const float* src_w2  = (const float*)d_in[6];
    const float* src_b2  = (const float*)d_in[7];
    const float* tar_w1  = (const float*)d_in[8];
    const float* tar_b1  = (const float*)d_in[9];
    const float* tar_w2  = (const float*)d_in[10];
    const float* tar_b2  = (const float*)d_in[11];
    const float* gru_wih = (const float*)d_in[12];
    const float* gru_whh = (const float*)d_in[13];
    const float* gru_bih = (const float*)d_in[14];
    const float* gru_bhh = (const float*)d_in[15];
    float* out = (float*)d_out;

    __nv_bfloat16 *pHh, *pHl, *pAGGh, *pAGGl;
    float *pMSG, *pG;
    cudaGetSymbolAddress((void**)&pHh, g_Hh);   cudaGetSymbolAddress((void**)&pHl, g_Hl);
    cudaGetSymbolAddress((void**)&pAGGh, g_AGGh); cudaGetSymbolAddress((void**)&pAGGl, g_AGGl);
    cudaGetSymbolAddress((void**)&pMSG, g_MSG); cudaGetSymbolAddress((void**)&pG, g_G);

    // 1) fused: MLP layer 1 (gather-fused, relu) + GRU gh half (independent)
    fused1_kernel<<<320, 256>>>(
        memory, dtv, source, target,
        src_w1, tar_w1, src_b1, tar_b1, pHh, pHl,
        gru_whh, gru_bhh, pG + (size_t)NN * K3);

    // 2) MLP layer 2: H[2048,256] -> MSG[2048,256] fp32
    tgemm_kernel<<<dim3(DD / 64, (2 * BB) / 64), 256>>>(
        pHh, pHl,
        pHh + (size_t)BB * DD, pHl + (size_t)BB * DD,
        src_w2, tar_w2,
        src_b2, tar_b2, pMSG, nullptr, nullptr, BB, DD, DD, 0);

    // 3) deterministic segment mean -> AGG hi/lo, CNT (warp per node)
    segment_kernel<<<NN / 8, 256>>>(source, target);

    // 4) GRU gi half: gi = agg@wih^T + bih  (M=1024, N=768, K=256)
    tgemm_kernel<<<dim3(K3 / 64, NN / 64), 256>>>(
        pAGGh, pAGGl,
        pAGGh, pAGGl,
        gru_wih, gru_wih,
        gru_bih, gru_bih, pG, nullptr, nullptr, NN, K3, DD, 0);

    // 5) gates + masked output
    gate_kernel<<<NN, DD>>>(memory, out);
}

// round 17
// speedup vs baseline: 1.7081x; 1.7081x over previous
#include <cuda_runtime.h>
#include <cuda_bf16.h>
#include <math.h>
#include <stdint.h>

// Problem constants
#define BB 1024   // batch (edges per direction)
#define NN 1024   // nodes
#define DD 256    // feature dim
#define K3 768    // 3*D

// ---------------- static scratch (no allocations allowed) ----------------
__device__ __nv_bfloat16 g_Hh[2 * BB * DD], g_Hl[2 * BB * DD];   // hidden hi/lo
__device__ float         g_MSG[2 * BB * DD];                     // messages fp32
__device__ __nv_bfloat16 g_AGGh[NN * DD], g_AGGl[NN * DD];       // segment mean hi/lo
__device__ float         g_G[2 * NN * K3];                       // gi | gh fp32
__device__ int           g_CNT[NN];

// ---------------- fp32 -> bf16 hi/lo split ----------------
__device__ __forceinline__ void split_bf16(float v, __nv_bfloat16& h, __nv_bfloat16& l) {
    h = __float2bfloat16(v);
    l = __float2bfloat16(v - __bfloat162float(h));
}
__device__ __forceinline__ uint32_t pack2(__nv_bfloat16 a, __nv_bfloat16 b) {
    __nv_bfloat162 t; t.x = a; t.y = b;
    return *reinterpret_cast<uint32_t*>(&t);
}

// ---------------- mma.sync bf16 helper ----------------
__device__ __forceinline__ void mma_bf16(float* c, const uint32_t* a, const uint32_t* b) {
    asm volatile(
        "mma.sync.aligned.m16n8k16.row.col.f32.bf16.bf16.f32 "
        "{%0,%1,%2,%3}, {%4,%5,%6,%7}, {%8,%9}, {%0,%1,%2,%3};\n"
        : "+f"(c[0]), "+f"(c[1]), "+f"(c[2]), "+f"(c[3])
        : "r"(a[0]), "r"(a[1]), "r"(a[2]), "r"(a[3]), "r"(b[0]), "r"(b[1]));
}

// ---------------- ldmatrix helper ----------------
__device__ __forceinline__ uint32_t smem_u32(const void* p) {
    return (uint32_t)__cvta_generic_to_shared(p);
}
#define LDSM_X4(r0, r1, r2, r3, addr) \
    asm volatile("ldmatrix.sync.aligned.m8n8.x4.shared.b16 {%0,%1,%2,%3}, [%4];" \
        : "=r"(r0), "=r"(r1), "=r"(r2), "=r"(r3) : "r"(addr))

#define SPAD 40

// ---- shared compute core: 3-term split MMA over one staged 64x32 chunk ----
// Fragment loads via ldmatrix.x4: 12 LDSM per chunk (vs 96 scalar LDS).
__device__ __forceinline__ void compute_chunk(
    const __nv_bfloat16* sAh, const __nv_bfloat16* sAl,
    const __nv_bfloat16* sWh, const __nv_bfloat16* sWl,
    float acc[2][2][4], int warp_m, int warp_n, int lane) {
    const int arow = warp_m * 32 + (lane & 15);
    const int acol = (lane >> 4) << 3;
    const int brow = warp_n * 16 + ((lane >> 4) << 3) + (lane & 7);
    const int bcol = ((lane >> 3) & 1) << 3;
#pragma unroll
    for (int ks = 0; ks < 2; ks++) {
        const int k0 = ks * 16;
        uint32_t ah[2][4], al[2][4], bh[4], bl[4];
#pragma unroll
        for (int mi = 0; mi < 2; mi++) {
            LDSM_X4(ah[mi][0], ah[mi][1], ah[mi][2], ah[mi][3],
                    smem_u32(&sAh[(arow + mi * 16) * SPAD + k0 + acol]));
            LDSM_X4(al[mi][0], al[mi][1], al[mi][2], al[mi][3],
                    smem_u32(&sAl[(arow + mi * 16) * SPAD + k0 + acol]));
        }
        LDSM_X4(bh[0], bh[1], bh[2], bh[3], smem_u32(&sWh[brow * SPAD + k0 + bcol]));
        LDSM_X4(bl[0], bl[1], bl[2], bl[3], smem_u32(&sWl[brow * SPAD + k0 + bcol]));
#pragma unroll
        for (int mi = 0; mi < 2; mi++)
#pragma unroll
            for (int ni = 0; ni < 2; ni++) {
                mma_bf16(acc[mi][ni], ah[mi], &bh[ni * 2]);
                mma_bf16(acc[mi][ni], ah[mi], &bl[ni * 2]);
                mma_bf16(acc[mi][ni], al[mi], &bh[ni * 2]);
            }
    }
}

// ---- epilogue helper ----
__device__ __forceinline__ void epilogue(
    float acc[2][2][4], const float* __restrict__ bias,
    float* __restrict__ Cf, __nv_bfloat16* __restrict__ Chi, __nv_bfloat16* __restrict__ Clo,
    int row0, int col0, int Nn, int doRelu, int warp_m, int warp_n, int gid, int tig) {
#pragma unroll
    for (int mi = 0; mi < 2; mi++) {
#pragma unroll
        for (int ni = 0; ni < 2; ni++) {
            const int r0 = row0 + warp_m * 32 + mi * 16 + gid;
            const int c  = col0 + warp_n * 16 + ni * 8 + tig * 2;
            const float bx = bias[c];
            const float by = bias[c + 1];
            float v0 = acc[mi][ni][0] + bx;
            float v1 = acc[mi][ni][1] + by;
            float v2 = acc[mi][ni][2] + bx;
            float v3 = acc[mi][ni][3] + by;
            if (doRelu) {
                v0 = fmaxf(v0, 0.0f); v1 = fmaxf(v1, 0.0f);
                v2 = fmaxf(v2, 0.0f); v3 = fmaxf(v3, 0.0f);
            }
            if (Cf) {
                *reinterpret_cast<float2*>(&Cf[(size_t)r0 * Nn + c])       = make_float2(v0, v1);
                *reinterpret_cast<float2*>(&Cf[(size_t)(r0 + 8) * Nn + c]) = make_float2(v2, v3);
            }
            if (Chi) {
                __nv_bfloat16 h0, l0, h1, l1;
                split_bf16(v0, h0, l0); split_bf16(v1, h1, l1);
                *reinterpret_cast<uint32_t*>(&Chi[(size_t)r0 * Nn + c]) = pack2(h0, h1);
                *reinterpret_cast<uint32_t*>(&Clo[(size_t)r0 * Nn + c]) = pack2(l0, l1);
                split_bf16(v2, h0, l0); split_bf16(v3, h1, l1);
                *reinterpret_cast<uint32_t*>(&Chi[(size_t)(r0 + 8) * Nn + c]) = pack2(h0, h1);
                *reinterpret_cast<uint32_t*>(&Clo[(size_t)(r0 + 8) * Nn + c]) = pack2(l0, l1);
            }
        }
    }
}

// ---- fp32 register pair + split-store ----
struct FpRegs { float4 f0, f1; };

__device__ __forceinline__ void store_fp(
    __nv_bfloat16* sh, __nv_bfloat16* sl, const FpRegs& r, int lr, int lk) {
    __nv_bfloat16 h0,l0,h1,l1,h2,l2,h3,l3,h4,l4,h5,l5,h6,l6,h7,l7;
    split_bf16(r.f0.x, h0, l0); split_bf16(r.f0.y, h1, l1);
    split_bf16(r.f0.z, h2, l2); split_bf16(r.f0.w, h3, l3);
    split_bf16(r.f1.x, h4, l4); split_bf16(r.f1.y, h5, l5);
    split_bf16(r.f1.z, h6, l6); split_bf16(r.f1.w, h7, l7);
    uint4 vh = make_uint4(pack2(h0,h1), pack2(h2,h3), pack2(h4,h5), pack2(h6,h7));
    uint4 vl = make_uint4(pack2(l0,l1), pack2(l2,l3), pack2(l4,l5), pack2(l6,l7));
    *reinterpret_cast<uint4*>(&sh[lr * SPAD + lk]) = vh;
    *reinterpret_cast<uint4*>(&sl[lr * SPAD + lk]) = vl;
}

// =============== GEMM1: gather-fused MLP layer 1 ===============
__global__ __launch_bounds__(256) void tgemm1_kernel(
    const float* __restrict__ memory, const float* __restrict__ dtv,
    const int* __restrict__ src, const int* __restrict__ tgt,
    const float* __restrict__ Wf0, const float* __restrict__ Wf1,
    const float* __restrict__ b0, const float* __restrict__ b1,
    __nv_bfloat16* __restrict__ Chi, __nv_bfloat16* __restrict__ Clo) {

    __shared__ __align__(16) __nv_bfloat16 sAh[64 * SPAD];
    __shared__ __align__(16) __nv_bfloat16 sAl[64 * SPAD];
    __shared__ __align__(16) __nv_bfloat16 sWh[64 * SPAD];
    __shared__ __align__(16) __nv_bfloat16 sWl[64 * SPAD];

    const int tid  = threadIdx.x;
    const int wid  = tid >> 5;
    const int lane = tid & 31;
    const int g8   = lane >> 2;
    const int tig  = lane & 3;
    const int warp_m = wid >> 2;
    const int warp_n = wid & 3;

    const int row0 = blockIdx.y * 64;
    const int col0 = blockIdx.x * 64;
    const bool hi2 = (row0 >= BB);
    const float* __restrict__ Wf = hi2 ? Wf1 : Wf0;
    const float* __restrict__ bias = hi2 ? b1 : b0;
    const int arow0 = row0 - (hi2 ? BB : 0);

    const int lr = tid >> 2;
    const int lk = (tid & 3) * 8;

    const int b = arow0 + lr;
    const int s = src[b];
    const int t = tgt[b];
    const float* base0 = memory + (size_t)(hi2 ? t : s) * DD;
    const float* base1 = memory + (size_t)(hi2 ? s : t) * DD;
    const float* base2 = dtv + ((size_t)b * NN + (hi2 ? t : s)) * DD;

    float acc[2][2][4];
#pragma unroll
    for (int mi = 0; mi < 2; mi++)
#pragma unroll
        for (int ni = 0; ni < 2; ni++)
#pragma unroll
            for (int j = 0; j < 4; j++) acc[mi][ni][j] = 0.0f;

    const int NC = K3 >> 5;
    FpRegs ra, rw;
    {
        const float* p = base0 + lk;
        ra.f0 = *reinterpret_cast<const float4*>(p);
        ra.f1 = *reinterpret_cast<const float4*>(p + 4);
        const float* q = &Wf[(size_t)(col0 + lr) * K3 + lk];
        rw.f0 = *reinterpret_cast<const float4*>(q);
        rw.f1 = *reinterpret_cast<const float4*>(q + 4);
    }

    for (int c = 0; c < NC; c++) {
        store_fp(sAh, sAl, ra, lr, lk);
        store_fp(sWh, sWl, rw, lr, lk);
        __syncthreads();

        if (c + 1 < NC) {
            const int kt = (c + 1) * 32;
            const int reg = kt >> 8;
            const int co  = (kt & 255) + lk;
            const float* p = (reg == 0 ? base0 : (reg == 1 ? base1 : base2)) + co;
            ra.f0 = *reinterpret_cast<const float4*>(p);
            ra.f1 = *reinterpret_cast<const float4*>(p + 4);
            const float* q = &Wf[(size_t)(col0 + lr) * K3 + kt + lk];
            rw.f0 = *reinterpret_cast<const float4*>(q);
            rw.f1 = *reinterpret_cast<const float4*>(q + 4);
        }

        compute_chunk(sAh, sAl, sWh, sWl, acc, warp_m, warp_n, lane);
        __syncthreads();
    }

    epilogue(acc, bias, nullptr, Chi, Clo, row0, col0, DD, 1, warp_m, warp_n, g8, tig);
}

// =============== generic dual-half GEMM (layers 2 and GRU) ===============
union LoadRegs {
    struct { uint4 vh, vl; } bf;
    FpRegs fp;
};

__device__ __forceinline__ void load_regs(
    LoadRegs& r,
    const __nv_bfloat16* __restrict__ gh, const __nv_bfloat16* __restrict__ gl,
    const float* __restrict__ gf,
    int grow0, int ld, int kt, int lr, int lk) {
    if (gf) {
        const float* p = &gf[(size_t)(grow0 + lr) * ld + kt + lk];
        r.fp.f0 = *reinterpret_cast<const float4*>(p);
        r.fp.f1 = *reinterpret_cast<const float4*>(p + 4);
    } else {
        r.bf.vh = *reinterpret_cast<const uint4*>(&gh[(size_t)(grow0 + lr) * ld + kt + lk]);
        r.bf.vl = *reinterpret_cast<const uint4*>(&gl[(size_t)(grow0 + lr) * ld + kt + lk]);
    }
}

__device__ __forceinline__ void store_regs(
    __nv_bfloat16* sh, __nv_bfloat16* sl, const LoadRegs& r,
    bool isFp, int lr, int lk) {
    if (isFp) {
        store_fp(sh, sl, r.fp, lr, lk);
    } else {
        *reinterpret_cast<uint4*>(&sh[lr * SPAD + lk]) = r.bf.vh;
        *reinterpret_cast<uint4*>(&sl[lr * SPAD + lk]) = r.bf.vl;
    }
}

__global__ __launch_bounds__(256) void tgemm_kernel(
    const __nv_bfloat16* __restrict__ Ah0, const __nv_bfloat16* __restrict__ Al0,
    const float* __restrict__ Af0,
    const __nv_bfloat16* __restrict__ Ah1, const __nv_bfloat16* __restrict__ Al1,
    const float* __restrict__ Af1,
    const float* __restrict__ Wf0, const float* __restrict__ Wf1,
    const float* __restrict__ b0, const float* __restrict__ b1,
    float* __restrict__ Cf, __nv_bfloat16* __restrict__ Chi, __nv_bfloat16* __restrict__ Clo,
    int halfM, int Nn, int Kk, int doRelu) {

    __shared__ __align__(16) __nv_bfloat16 sAh[64 * SPAD];
    __shared__ __align__(16) __nv_bfloat16 sAl[64 * SPAD];
    __shared__ __align__(16) __nv_bfloat16 sWh[64 * SPAD];
    __shared__ __align__(16) __nv_bfloat16 sWl[64 * SPAD];

    const int tid  = threadIdx.x;
    const int wid  = tid >> 5;
    const int lane = tid & 31;
    const int g8   = lane >> 2;
    const int tig  = lane & 3;
    const int warp_m = wid >> 2;
    const int warp_n = wid & 3;

    const int row0 = blockIdx.y * 64;
    const int col0 = blockIdx.x * 64;
    const bool hi2 = (row0 >= halfM);
    const __nv_bfloat16* __restrict__ Ah = hi2 ? Ah1 : Ah0;
    const __nv_bfloat16* __restrict__ Al = hi2 ? Al1 : Al0;
    const float* __restrict__ Af = hi2 ? Af1 : Af0;
    const float* __restrict__ Wf = hi2 ? Wf1 : Wf0;
    const float* __restrict__ bias = hi2 ? b1 : b0;
    const int arow0 = row0 - (hi2 ? halfM : 0);
    const bool aFp = (Af != nullptr);

    float acc[2][2][4];
#pragma unroll
    for (int mi = 0; mi < 2; mi++)
#pragma unroll
        for (int ni = 0; ni < 2; ni++)
#pragma unroll
            for (int j = 0; j < 4; j++) acc[mi][ni][j] = 0.0f;

    const int lr = tid >> 2;
    const int lk = (tid & 3) * 8;

    const int NC = Kk >> 5;
    LoadRegs ra, rw;
    load_regs(ra, Ah, Al, Af, arow0, Kk, 0, lr, lk);
    load_regs(rw, nullptr, nullptr, Wf, col0, Kk, 0, lr, lk);

    for (int c = 0; c < NC; c++) {
        store_regs(sAh, sAl, ra, aFp, lr, lk);
        store_regs(sWh, sWl, rw, true, lr, lk);
        __syncthreads();

        if (c + 1 < NC) {
            const int kt = (c + 1) * 32;
            load_regs(ra, Ah, Al, Af, arow0, Kk, kt, lr, lk);
            load_regs(rw, nullptr, nullptr, Wf, col0, Kk, kt, lr, lk);
        }

        compute_chunk(sAh, sAl, sWh, sWl, acc, warp_m, warp_n, lane);
        __syncthreads();
    }

    epilogue(acc, bias, Cf, Chi, Clo, row0, col0, Nn, doRelu, warp_m, warp_n, g8, tig);
}

// ---------------- deterministic segment mean (warp-per-node) ----------------
__global__ __launch_bounds__(256) void segment_kernel(const int* __restrict__ src,
                                                      const int* __restrict__ tgt) {
    __shared__ int s_ids[2 * BB];
    const int tid = threadIdx.x;
    const int wid = tid >> 5;
    const int lid = tid & 31;
    const int node = blockIdx.x * 8 + wid;

#pragma unroll
    for (int i = 0; i < 8; i++) {
        int e = tid + i * 256;
        s_ids[e] = (e < BB) ? src[e] : tgt[e - BB];
    }
    __syncthreads();

    float sum[8] = {0, 0, 0, 0, 0, 0, 0, 0};
    int cnt = 0;
#pragma unroll 4
    for (int base = 0; base < 2 * BB; base += 32) {
        int v = s_ids[base + lid];
        unsigned m = __ballot_sync(0xffffffffu, v == node);
        while (m) {
            int bpos = __ffs(m) - 1;
            m &= m - 1;
            int e = base + bpos;
            const float4* p = reinterpret_cast<const float4*>(&g_MSG[(size_t)e * DD + lid * 8]);
            float4 a = p[0];
            float4 q = p[1];
            sum[0] += a.x; sum[1] += a.y; sum[2] += a.z; sum[3] += a.w;
            sum[4] += q.x; sum[5] += q.y; sum[6] += q.z; sum[7] += q.w;
            cnt++;
        }
    }

    const float denom = (cnt > 0) ? (float)cnt : 1.0f;
    uint32_t ph[4], pl[4];
#pragma unroll
    for (int j = 0; j < 4; j++) {
        __nv_bfloat16 h0, l0, h1, l1;
        split_bf16(sum[2 * j] / denom, h0, l0);
        split_bf16(sum[2 * j + 1] / denom, h1, l1);
        ph[j] = pack2(h0, h1);
        pl[j] = pack2(l0, l1);
    }
    *reinterpret_cast<uint4*>(&g_AGGh[(size_t)node * DD + lid * 8]) =
        make_uint4(ph[0], ph[1], ph[2], ph[3]);
    *reinterpret_cast<uint4*>(&g_AGGl[(size_t)node * DD + lid * 8]) =
        make_uint4(pl[0], pl[1], pl[2], pl[3]);
    if (lid == 0) g_CNT[node] = cnt;
}

// ---------------- GRU gates + masked write ----------------
__global__ void gate_kernel(const float* __restrict__ memory,
                            float* __restrict__ out) {
    const int n = blockIdx.x;
    const int d = threadIdx.x;
    const float* gi = g_G + (size_t)n * K3;
    const float* gh = g_G + (size_t)(NN + n) * K3;

    float r  = 1.0f / (1.0f + expf(-(gi[d] + gh[d])));
    float z  = 1.0f / (1.0f + expf(-(gi[DD + d] + gh[DD + d])));
    float nn = tanhf(gi[2 * DD + d] + r * gh[2 * DD + d]);
    float h  = memory[(size_t)n * DD + d];
    float nv = (1.0f - z) * nn + z * h;
    out[(size_t)n * DD + d] = (g_CNT[n] > 0) ? nv : h;
}

// ---------------- launch ----------------
extern "C" void kernel_launch(void* const* d_in, const int* in_sizes, int n_in,
                              void* d_out, int out_size) {
    const float* memory  = (const float*)d_in[0];
    const int*   source  = (const int*)d_in[1];
    const int*   target  = (const int*)d_in[2];
    const float* dtv     = (const float*)d_in[3];
    const float* src_w1  = (const float*)d_in[4];
    const float* src_b1  = (const float*)d_in[5];
    const float* src_w2  = (const float*)d_in[6];
    const float* src_b2  = (const float*)d_in[7];
    const float* tar_w1  = (const float*)d_in[8];
    const float* tar_b1  = (const float*)d_in[9];
    const float* tar_w2  = (const float*)d_in[10];
    const float* tar_b2  = (const float*)d_in[11];
    const float* gru_wih = (const float*)d_in[12];
    const float* gru_whh = (const float*)d_in[13];
    const float* gru_bih = (const float*)d_in[14];
    const float* gru_bhh = (const float*)d_in[15];
    float* out = (float*)d_out;

    __nv_bfloat16 *pHh, *pHl, *pAGGh, *pAGGl;
    float *pMSG, *pG;
    cudaGetSymbolAddress((void**)&pHh, g_Hh);   cudaGetSymbolAddress((void**)&pHl, g_Hl);
    cudaGetSymbolAddress((void**)&pAGGh, g_AGGh); cudaGetSymbolAddress((void**)&pAGGl, g_AGGl);
    cudaGetSymbolAddress((void**)&pMSG, g_MSG); cudaGetSymbolAddress((void**)&pG, g_G);

    // 1) MLP layer 1 (relu), gather fused into A staging: -> H[2048,256] bf16 hi/lo
    tgemm1_kernel<<<dim3(DD / 64, (2 * BB) / 64), 256>>>(
        memory, dtv, source, target,
        src_w1, tar_w1, src_b1, tar_b1, pHh, pHl);

    // 2) MLP layer 2: H[2048,256] -> MSG[2048,256] fp32
    tgemm_kernel<<<dim3(DD / 64, (2 * BB) / 64), 256>>>(
        pHh, pHl, nullptr,
        pHh + (size_t)BB * DD, pHl + (size_t)BB * DD, nullptr,
        src_w2, tar_w2,
        src_b2, tar_b2, pMSG, nullptr, nullptr, BB, DD, DD, 0);

    // 3) deterministic segment mean -> AGG hi/lo, CNT (warp per node)
    segment_kernel<<<NN / 8, 256>>>(source, target);

    // 4) GRU preactivations: gi = agg@wih^T + bih ; gh = memory@whh^T + bhh
    tgemm_kernel<<<dim3(K3 / 64, (2 * NN) / 64), 256>>>(
        pAGGh, pAGGl, nullptr,
        nullptr, nullptr, memory,
        gru_wih, gru_whh,
        gru_bih, gru_bhh, pG, nullptr, nullptr, NN, K3, DD, 0);

    // 5) gates + masked output
    gate_kernel<<<NN, DD>>>(memory, out);
}